// round 16
// baseline (speedup 1.0000x reference)
#include <cuda_runtime.h>
#include <cuda_bf16.h>
#include <cuda_fp16.h>

#define N_USER  50000
#define N_ITEM  100000
#define N_NODES 150000
#define DD      64
#define NLAYER  3
#define NNZ     2400000
#define BB      1024
#define NB_SCAN 587   // ceil(N_NODES/256)
#define WP2     32    // uint2 pairs per n row (global, compact)
#define SP2     36    // smem pitch in uint2 (bank-conflict-free)

#define NB_INIT   9375   // (N_NODES*16)/256 float4 slots
#define NB_WSPLIT 24     // ceil(NLAYER*64*32/256)
#define NB_MLP    256    // 1024 samples, 4 per 256-thread block
#define NB_HIST   9375   // ceil(NNZ/256)
#define NB_APPLY  256    // 1024 samples, 4 per block
#define NB_SPMM   4688   // ceil((N_NODES/4 warps)/8 per block)
#define NB_GATHER 384    // 3*BB warps / 8 per block

// Scratch (device globals: allocation-free per harness rules)
__device__ float4 g_E [N_NODES * 16];   // E  [N,64] fp32
__device__ float4 g_LE[N_NODES * 16];   // L_E[N,64] fp32
__device__ uint2  g_Eh[N_NODES * 16];   // E  [N,64] fp16 shadow (4 halves/uint2)
__device__ float  g_mlp[BB * DD];
__device__ int    g_win[N_USER];
// CSR scratch
__device__ int    g_cnt[N_NODES];
__device__ int    g_ptr[N_NODES];
__device__ int    g_cur[N_NODES];
__device__ int    g_bsum[NB_SCAN];
__device__ int    g_bscan[NB_SCAN];
__device__ int2   g_cv[NNZ];            // {col, float_as_int(val)}
// bf16 double-split weights, PAIR-PACKED: entry j=kk*4+q holds pairs (kp, kp+4)
// where kp = kk*8+q.  [layer][n(64)][32 uint2]
__device__ uint2  g_whiP[NLAYER * 64 * WP2];
__device__ uint2  g_wloP[NLAYER * 64 * WP2];

// split x into bf16 hi + bf16 lo (pairwise packed, low half = first elem)
__device__ __forceinline__ void split_pack(float a, float b,
                                           unsigned int& hi, unsigned int& lo) {
    __nv_bfloat162 h = __floats2bfloat162_rn(a, b);
    float ra = a - __low2float(h);
    float rb = b - __high2float(h);
    __nv_bfloat162 l = __floats2bfloat162_rn(ra, rb);
    hi = *reinterpret_cast<unsigned int*>(&h);
    lo = *reinterpret_cast<unsigned int*>(&l);
}

__device__ __forceinline__ uint2 pack_half4(float4 v) {
    __half2 a = __floats2half2_rn(v.x, v.y);
    __half2 b = __floats2half2_rn(v.z, v.w);
    uint2 r;
    r.x = *reinterpret_cast<unsigned int*>(&a);
    r.y = *reinterpret_cast<unsigned int*>(&b);
    return r;
}
// accumulate 8 halves (uint4) scaled by v into two float4 accumulators
__device__ __forceinline__ void acc8(float4& a, float4& b, float v, uint4 u) {
    float2 f0 = __half22float2(*reinterpret_cast<__half2*>(&u.x));
    float2 f1 = __half22float2(*reinterpret_cast<__half2*>(&u.y));
    float2 f2 = __half22float2(*reinterpret_cast<__half2*>(&u.z));
    float2 f3 = __half22float2(*reinterpret_cast<__half2*>(&u.w));
    a.x += v * f0.x; a.y += v * f0.y; a.z += v * f1.x; a.w += v * f1.y;
    b.x += v * f2.x; b.y += v * f2.y; b.z += v * f3.x; b.w += v * f3.y;
}

// ================= K_setup: init E + zero cnt + win_reset + wsplit + mlp ======
__global__ void __launch_bounds__(256) k_setup(
    const float4* __restrict__ ue, const float4* __restrict__ ie,
    const int* __restrict__ ui,
    const float* __restrict__ w1, const float* __restrict__ w2,
    const float* __restrict__ feat,
    const float* __restrict__ l1w, const float* __restrict__ l1b,
    const float* __restrict__ l2w, const float* __restrict__ l2b) {
    int b = blockIdx.x;
    int t = threadIdx.x;
    if (b < NB_INIT) {                                   // ---- E init (fp32+fp16)
        int i = b * 256 + t;
        const int NU4 = N_USER * 16;
        if (i >= N_NODES * 16) return;
        float4 v = (i < NU4) ? ue[i] : ie[i - NU4];
        g_E[i] = v;
        g_Eh[i] = pack_half4(v);
        return;
    }
    b -= NB_INIT;
    if (b < NB_SCAN) {                                   // ---- cnt zero
        int i = b * 256 + t;
        if (i < N_NODES) g_cnt[i] = 0;
        return;
    }
    b -= NB_SCAN;
    if (b < 4) {                                         // ---- win reset
        int i = b * 256 + t;
        if (i < BB) g_win[ui[i]] = -1;
        return;
    }
    b -= 4;
    if (b < NB_WSPLIT) {                                 // ---- w split (pair-packed)
        int idx = b * 256 + t;
        if (idx >= NLAYER * 64 * WP2) return;
        int layer = idx / (64 * WP2);
        int rem = idx % (64 * WP2);
        int n = rem >> 5, j = rem & 31;
        int kk = j >> 2, q = j & 3;
        int kp0 = kk * 8 + q, kp1 = kp0 + 4;
        const float* W1 = w1 + layer * 4096;
        const float* W2 = w2 + layer * 4096;
        // element column k (of 128) -> w value at [k][n]
        int ka = 2 * kp0, kb = 2 * kp0 + 1, kc = 2 * kp1, kd = 2 * kp1 + 1;
        float wa = (ka < 64) ? W1[ka * 64 + n] : W2[(ka - 64) * 64 + n];
        float wb = (kb < 64) ? W1[kb * 64 + n] : W2[(kb - 64) * 64 + n];
        float wc = (kc < 64) ? W1[kc * 64 + n] : W2[(kc - 64) * 64 + n];
        float wd = (kd < 64) ? W1[kd * 64 + n] : W2[(kd - 64) * 64 + n];
        unsigned int hi0, lo0, hi1, lo1;
        split_pack(wa, wb, hi0, lo0);
        split_pack(wc, wd, hi1, lo1);
        int o = (layer * 64 + n) * WP2 + j;
        g_whiP[o] = make_uint2(hi0, hi1);
        g_wloP[o] = make_uint2(lo0, lo1);
        return;
    }
    b -= NB_WSPLIT;
    {                                                    // ---- mlp (4 samples/block)
        __shared__ float h[4][32];
        int s = t >> 6, u = t & 63;                      // sample slot, within
        int i = b * 4 + s;
        if (u < 32) {
            float acc = l1b[u];
#pragma unroll
            for (int f = 0; f < 4; f++) acc += feat[i * 4 + f] * l1w[f * 32 + u];
            h[s][u] = acc;
        }
        __syncthreads();
        float acc = l2b[u];
#pragma unroll
        for (int j = 0; j < 32; j++) acc += h[s][j] * l2w[j * DD + u];
        g_mlp[i * DD + u] = acc;
    }
}

// ================= K_hist2: histogram + win_max ===============================
__global__ void __launch_bounds__(256) k_hist2(const int* __restrict__ row,
                                               const int* __restrict__ ui) {
    int b = blockIdx.x;
    int t = threadIdx.x;
    if (b < NB_HIST) {
        int e = b * 256 + t;
        if (e < NNZ) atomicAdd(&g_cnt[row[e]], 1);
        return;
    }
    b -= NB_HIST;
    int i = b * 256 + t;
    if (i < BB) atomicMax(&g_win[ui[i]], i);
}

// ================= scans =================
__global__ void k_scan1() {
    __shared__ int s[256];
    int t = threadIdx.x;
    int i = blockIdx.x * 256 + t;
    int v = (i < N_NODES) ? g_cnt[i] : 0;
    s[t] = v;
    __syncthreads();
#pragma unroll
    for (int off = 1; off < 256; off <<= 1) {
        int u = (t >= off) ? s[t - off] : 0;
        __syncthreads();
        s[t] += u;
        __syncthreads();
    }
    if (i < N_NODES) g_ptr[i] = s[t] - v;
    if (t == 255) g_bsum[blockIdx.x] = s[255];
}
__global__ void k_scan2() {
    __shared__ int s[1024];
    int t = threadIdx.x;
    int v = (t < NB_SCAN) ? g_bsum[t] : 0;
    s[t] = v;
    __syncthreads();
#pragma unroll
    for (int off = 1; off < 1024; off <<= 1) {
        int u = (t >= off) ? s[t - off] : 0;
        __syncthreads();
        s[t] += u;
        __syncthreads();
    }
    if (t < NB_SCAN) g_bscan[t] = s[t] - v;
}
__global__ void k_scan3() {
    int i = blockIdx.x * blockDim.x + threadIdx.x;
    if (i < N_NODES) {
        int p = g_ptr[i] + g_bscan[i >> 8];
        g_ptr[i] = p;
        g_cur[i] = p;
    }
}

// ================= K_fill2: CSR fill + user-update apply ======================
__global__ void __launch_bounds__(256) k_fill2(const int* __restrict__ row,
                                               const int* __restrict__ col,
                                               const float* __restrict__ val,
                                               const int* __restrict__ ui,
                                               const float* __restrict__ user_emb,
                                               const float* __restrict__ ratio) {
    int b = blockIdx.x;
    int t = threadIdx.x;
    if (b < NB_HIST) {                                   // ---- fill
        int e = b * 256 + t;
        if (e >= NNZ) return;
        int r = row[e];
        int pos = atomicAdd(&g_cur[r], 1);
        g_cv[pos] = make_int2(col[e], __float_as_int(val[e]));
        return;
    }
    b -= NB_HIST;
    {                                                    // ---- apply (4 samples/block)
        int s = t >> 6, u64 = t & 63;
        int i = b * 4 + s;
        int u = ui[i];
        if (g_win[u] != i) return;
        float r = *ratio;
        float* E = (float*)g_E;
        float v = user_emb[u * DD + u64] * (1.0f - r) + g_mlp[i * DD + u64] * r;
        E[u * DD + u64] = v;
        ((__half*)g_Eh)[u * DD + u64] = __float2half_rn(v);
    }
}

// ---------------- gather body (device fn) ----------------
__device__ __forceinline__ void gather_body(int w, int lane,
                                            const int* __restrict__ user_idx,
                                            const int* __restrict__ pos_idx,
                                            const int* __restrict__ neg_idx,
                                            float* __restrict__ out, int layer) {
    if (w >= 3 * BB) return;
    int node;
    if (w < BB)          node = user_idx[w];
    else if (w < 2 * BB) node = N_USER + pos_idx[w - BB];
    else                 node = N_USER + neg_idx[w - 2 * BB];
    float2 v = ((const float2*)g_E)[node * 32 + lane];
    float scale = 1.0f;
    if (layer > 0) {
        float s = v.x * v.x + v.y * v.y;
#pragma unroll
        for (int o = 16; o; o >>= 1) s += __shfl_xor_sync(0xffffffffu, s, o);
        scale = 1.0f / fmaxf(sqrtf(s), 1e-12f);
    }
    ((float2*)(out + (size_t)w * 256 + layer * 64))[lane] = make_float2(v.x * scale, v.y * scale);
}

__global__ void k_gather(const int* __restrict__ user_idx, const int* __restrict__ pos_idx,
                         const int* __restrict__ neg_idx, float* __restrict__ out, int layer) {
    int w = (blockIdx.x * blockDim.x + threadIdx.x) >> 5;
    gather_body(w, threadIdx.x & 31, user_idx, pos_idx, neg_idx, out, layer);
}

// ================= CSR SpMM (fp16 gather): 4 rows/warp, unroll 2 ==============
// blocks [0, NB_SPMM): spmm; blocks [NB_SPMM, +NB_GATHER): gather prev output
__global__ void __launch_bounds__(256) k_spmm_g(const int* __restrict__ user_idx,
                                                const int* __restrict__ pos_idx,
                                                const int* __restrict__ neg_idx,
                                                float* __restrict__ out, int layer) {
    int lane = threadIdx.x & 31;
    if (blockIdx.x >= NB_SPMM) {
        if (layer >= 0) {
            int w = ((blockIdx.x - NB_SPMM) * blockDim.x + threadIdx.x) >> 5;
            gather_body(w, lane, user_idx, pos_idx, neg_idx, out, layer);
        }
        return;
    }
    int w = (blockIdx.x * blockDim.x + threadIdx.x) >> 5;
    int sub = lane >> 3;        // 0..3: row within warp
    int hl = lane & 7;          // uint4 slot within fp16 row (8 halves each)
    int row = w * 4 + sub;
    if (row >= N_NODES) return;
    int start = g_ptr[row];
    int end = start + g_cnt[row];
    const uint4* __restrict__ Eh = (const uint4*)g_Eh;

    float4 aL0 = make_float4(0.f, 0.f, 0.f, 0.f);
    float4 aH0 = make_float4(0.f, 0.f, 0.f, 0.f);
    float4 aL1 = make_float4(0.f, 0.f, 0.f, 0.f);
    float4 aH1 = make_float4(0.f, 0.f, 0.f, 0.f);
    int e = start;
    for (; e + 2 <= end; e += 2) {
        int2 c0 = g_cv[e], c1 = g_cv[e + 1];
        uint4 x0 = Eh[c0.x * 8 + hl];       // full 128B row per 8 lanes
        uint4 x1 = Eh[c1.x * 8 + hl];
        acc8(aL0, aH0, __int_as_float(c0.y), x0);
        acc8(aL1, aH1, __int_as_float(c1.y), x1);
    }
    if (e < end) {
        int2 c0 = g_cv[e];
        uint4 x0 = Eh[c0.x * 8 + hl];
        acc8(aL0, aH0, __int_as_float(c0.y), x0);
    }
    aL0.x += aL1.x; aL0.y += aL1.y; aL0.z += aL1.z; aL0.w += aL1.w;
    aH0.x += aH1.x; aH0.y += aH1.y; aH0.z += aH1.z; aH0.w += aH1.w;
    // lane owns halves [hl*8, hl*8+8) = float4 slots 2*hl, 2*hl+1
    g_LE[row * 16 + 2 * hl] = aL0;
    g_LE[row * 16 + 2 * hl + 1] = aH0;
}

// ================= tensor-core GEMM (bf16 double-split, m16n8k16) =============
// B operands pair-packed: one LDS.64 + one LDG.64 per (kk,nt) instead of 4 loads
#define MMA_BF16(C, A0, A1, A2, A3, B0, B1)                                      \
    asm volatile("mma.sync.aligned.m16n8k16.row.col.f32.bf16.bf16.f32 "          \
                 "{%0,%1,%2,%3}, {%4,%5,%6,%7}, {%8,%9}, {%0,%1,%2,%3};"         \
                 : "+f"(C[0]), "+f"(C[1]), "+f"(C[2]), "+f"(C[3])                \
                 : "r"(A0), "r"(A1), "r"(A2), "r"(A3), "r"(B0), "r"(B1))

__global__ void __launch_bounds__(256) k_gemm_mma(int layer,
                                                  const float* __restrict__ b1,
                                                  const float* __restrict__ b2) {
    __shared__ uint2 whiS[64 * SP2];   // pitched: conflict-free LDS.64
    __shared__ float bs[64];
    int t = threadIdx.x;
    {
        const uint2* src = g_whiP + layer * 64 * WP2;
        for (int i = t; i < 64 * WP2; i += 256) {
            int n = i >> 5, c = i & 31;
            whiS[n * SP2 + c] = src[i];
        }
        if (t < 64) bs[t] = b1[t] + b2[t];
    }
    __syncthreads();

    int warp = t >> 5, lane = t & 31;
    int q = lane & 3, g = lane >> 2;
    int base = blockIdx.x * 128 + warp * 16;
    int r0 = base + g, r1 = base + g + 8;
    int r0c = min(r0, N_NODES - 1), r1c = min(r1, N_NODES - 1);
    const float* __restrict__ Ei = (const float*)g_E;
    const float* __restrict__ LE = (const float*)g_LE;
    const uint2* __restrict__ wloP = g_wloP + layer * 64 * WP2;

    float C[8][4];
#pragma unroll
    for (int i = 0; i < 8; i++)
#pragma unroll
        for (int j = 0; j < 4; j++) C[i][j] = 0.f;

#pragma unroll
    for (int kk = 0; kk < 8; kk++) {         // kk16 chunks of K=128
        int half = kk >> 2;                  // 0: (LE+E), 1: (LE*E)
        int cb = (kk & 3) * 16;
        int cA = cb + 2 * q;
        int cB = cA + 8;
        float2 lA0 = *(const float2*)(LE + r0c * 64 + cA);
        float2 lB0 = *(const float2*)(LE + r0c * 64 + cB);
        float2 lA1 = *(const float2*)(LE + r1c * 64 + cA);
        float2 lB1 = *(const float2*)(LE + r1c * 64 + cB);
        float2 eA0 = *(const float2*)(Ei + r0c * 64 + cA);
        float2 eB0 = *(const float2*)(Ei + r0c * 64 + cB);
        float2 eA1 = *(const float2*)(Ei + r1c * 64 + cA);
        float2 eB1 = *(const float2*)(Ei + r1c * 64 + cB);
        float2 xA0, xB0, xA1, xB1;
        if (half) {
            xA0 = make_float2(lA0.x * eA0.x, lA0.y * eA0.y);
            xB0 = make_float2(lB0.x * eB0.x, lB0.y * eB0.y);
            xA1 = make_float2(lA1.x * eA1.x, lA1.y * eA1.y);
            xB1 = make_float2(lB1.x * eB1.x, lB1.y * eB1.y);
        } else {
            xA0 = make_float2(lA0.x + eA0.x, lA0.y + eA0.y);
            xB0 = make_float2(lB0.x + eB0.x, lB0.y + eB0.y);
            xA1 = make_float2(lA1.x + eA1.x, lA1.y + eA1.y);
            xB1 = make_float2(lB1.x + eB1.x, lB1.y + eB1.y);
        }
        unsigned int ah0, ah1, ah2, ah3, al0, al1, al2, al3;
        split_pack(xA0.x, xA0.y, ah0, al0);
        split_pack(xA1.x, xA1.y, ah1, al1);
        split_pack(xB0.x, xB0.y, ah2, al2);
        split_pack(xB1.x, xB1.y, ah3, al3);
        int kp = kk * 4 + q;                 // pair-packed index
#pragma unroll
        for (int nt = 0; nt < 8; nt++) {
            uint2 bh = whiS[(nt * 8 + g) * SP2 + kp];
            uint2 bl = __ldg(&wloP[(nt * 8 + g) * WP2 + kp]);
            MMA_BF16(C[nt], ah0, ah1, ah2, ah3, bh.x, bh.y);
            MMA_BF16(C[nt], al0, al1, al2, al3, bh.x, bh.y);
            MMA_BF16(C[nt], ah0, ah1, ah2, ah3, bl.x, bl.y);
        }
    }

    float* Eo = (float*)g_E;
    __half2* Eoh = (__half2*)g_Eh;
#pragma unroll
    for (int nt = 0; nt < 8; nt++) {
        int col = nt * 8 + 2 * q;
        float b0v = bs[col], b1v = bs[col + 1];
        float v00 = C[nt][0] + b0v, v01 = C[nt][1] + b1v;
        float v10 = C[nt][2] + b0v, v11 = C[nt][3] + b1v;
        v00 = v00 >= 0.f ? v00 : 0.2f * v00;
        v01 = v01 >= 0.f ? v01 : 0.2f * v01;
        v10 = v10 >= 0.f ? v10 : 0.2f * v10;
        v11 = v11 >= 0.f ? v11 : 0.2f * v11;
        if (r0 < N_NODES) {
            *(float2*)(Eo + r0 * 64 + col) = make_float2(v00, v01);
            Eoh[r0 * 32 + col / 2] = __floats2half2_rn(v00, v01);
        }
        if (r1 < N_NODES) {
            *(float2*)(Eo + r1 * 64 + col) = make_float2(v10, v11);
            Eoh[r1 * 32 + col / 2] = __floats2half2_rn(v10, v11);
        }
    }
}

extern "C" void kernel_launch(void* const* d_in, const int* in_sizes, int n_in,
                              void* d_out, int out_size) {
    const float *user_emb, *item_emb, *lin1_w, *lin1_b, *lin2_w, *lin2_b;
    const float *w1, *b1, *w2, *b2, *lap_val, *user_feat, *mlp_ratio;
    const int *lap_row, *lap_col, *user_idx, *pos_idx, *neg_idx;

    if (in_sizes[2] == 4096) {
        user_emb = (const float*)d_in[0];  item_emb = (const float*)d_in[1];
        user_feat= (const float*)d_in[2];
        lin1_w   = (const float*)d_in[3];  lin1_b   = (const float*)d_in[4];
        lin2_w   = (const float*)d_in[5];  lin2_b   = (const float*)d_in[6];
        w1 = (const float*)d_in[7];  b1 = (const float*)d_in[8];
        w2 = (const float*)d_in[9];  b2 = (const float*)d_in[10];
        lap_val  = (const float*)d_in[11]; mlp_ratio = (const float*)d_in[12];
        lap_row  = (const int*)d_in[13];   lap_col   = (const int*)d_in[14];
        user_idx = (const int*)d_in[15];   pos_idx   = (const int*)d_in[16];
        neg_idx  = (const int*)d_in[17];
    } else {
        user_emb = (const float*)d_in[0];  item_emb = (const float*)d_in[1];
        lin1_w   = (const float*)d_in[2];  lin1_b   = (const float*)d_in[3];
        lin2_w   = (const float*)d_in[4];  lin2_b   = (const float*)d_in[5];
        w1 = (const float*)d_in[6];  b1 = (const float*)d_in[7];
        w2 = (const float*)d_in[8];  b2 = (const float*)d_in[9];
        lap_row  = (const int*)d_in[10];   lap_col  = (const int*)d_in[11];
        lap_val  = (const float*)d_in[12];
        user_idx = (const int*)d_in[13];   user_feat = (const float*)d_in[14];
        pos_idx  = (const int*)d_in[15];   neg_idx   = (const int*)d_in[16];
        mlp_ratio= (const float*)d_in[17];
    }

    float* out = (float*)d_out;

    // phase 1: all independent setup work in one launch
    k_setup<<<NB_INIT + NB_SCAN + 4 + NB_WSPLIT + NB_MLP, 256>>>(
        (const float4*)user_emb, (const float4*)item_emb, user_idx,
        w1, w2, user_feat, lin1_w, lin1_b, lin2_w, lin2_b);
    // phase 2: histogram + winner selection
    k_hist2<<<NB_HIST + 4, 256>>>(lap_row, user_idx);
    // phase 3: scan chain
    k_scan1<<<NB_SCAN, 256>>>();
    k_scan2<<<1, 1024>>>();
    k_scan3<<<NB_SCAN, 256>>>();
    // phase 4: CSR fill + user-update apply
    k_fill2<<<NB_HIST + NB_APPLY, 256>>>(lap_row, lap_col, lap_val,
                                         user_idx, user_emb, mlp_ratio);
    // layer-0 gather
    k_gather<<<NB_GATHER, 256>>>(user_idx, pos_idx, neg_idx, out, 0);

    for (int k = 0; k < NLAYER; k++) {
        // spmm(k) fused with gather of layer-k output (k>0); layer=-1 disables
        k_spmm_g<<<NB_SPMM + NB_GATHER, 256>>>(user_idx, pos_idx, neg_idx, out,
                                               (k > 0) ? k : -1);
        k_gemm_mma<<<(N_NODES + 127) / 128, 256>>>(k, b1 + k * 64, b2 + k * 64);
    }
    // final gather after last gemm
    k_gather<<<NB_GATHER, 256>>>(user_idx, pos_idx, neg_idx, out, NLAYER);
}

// round 17
// speedup vs baseline: 1.0705x; 1.0705x over previous
#include <cuda_runtime.h>
#include <cuda_bf16.h>
#include <cuda_fp16.h>

#define N_USER  50000
#define N_ITEM  100000
#define N_NODES 150000
#define DD      64
#define NLAYER  3
#define NNZ     2400000
#define BB      1024
#define NB_SCAN 587   // ceil(N_NODES/256)
#define WPITCHB 68    // bf16-pair pitch per n row (64 pairs + 4 pad)

#define NB_INIT   9375   // (N_NODES*16)/256 float4 slots
#define NB_WSPLIT 48     // ceil(NLAYER*64*64/256)
#define NB_MLP    256    // 1024 samples, 4 per 256-thread block
#define NB_HIST   9375   // ceil(NNZ/256)
#define NB_APPLY  256    // 1024 samples, 4 per block
#define NB_SPMM   4688   // ceil((N_NODES/4 warps)/8 per block)
#define NB_GATHER 384    // 3*BB warps / 8 per block

// Scratch (device globals: allocation-free per harness rules)
__device__ float4 g_E [N_NODES * 16];   // E  [N,64] fp32
__device__ float4 g_LE[N_NODES * 16];   // L_E[N,64] fp32
__device__ uint2  g_Eh[N_NODES * 16];   // E  [N,64] fp16 shadow (4 halves/uint2)
__device__ float  g_mlp[BB * DD];
__device__ int    g_win[N_USER];
// CSR scratch
__device__ int    g_cnt[N_NODES];
__device__ int    g_ptr[N_NODES];
__device__ int    g_cur[N_NODES];
__device__ int    g_bsum[NB_SCAN];
__device__ int    g_bscan[NB_SCAN];
__device__ int2   g_cv[NNZ];            // {col, float_as_int(val)}
// bf16 double-split transposed weights: [layer][n(64)][pair k/2 padded to 68]
__device__ unsigned int g_whiB[NLAYER * 64 * WPITCHB];
__device__ unsigned int g_wloB[NLAYER * 64 * WPITCHB];

// split x into bf16 hi + bf16 lo (pairwise packed, low half = first elem)
__device__ __forceinline__ void split_pack(float a, float b,
                                           unsigned int& hi, unsigned int& lo) {
    __nv_bfloat162 h = __floats2bfloat162_rn(a, b);
    float ra = a - __low2float(h);
    float rb = b - __high2float(h);
    __nv_bfloat162 l = __floats2bfloat162_rn(ra, rb);
    hi = *reinterpret_cast<unsigned int*>(&h);
    lo = *reinterpret_cast<unsigned int*>(&l);
}

__device__ __forceinline__ uint2 pack_half4(float4 v) {
    __half2 a = __floats2half2_rn(v.x, v.y);
    __half2 b = __floats2half2_rn(v.z, v.w);
    uint2 r;
    r.x = *reinterpret_cast<unsigned int*>(&a);
    r.y = *reinterpret_cast<unsigned int*>(&b);
    return r;
}
// accumulate 8 halves (uint4) scaled by v into two float4 accumulators
__device__ __forceinline__ void acc8(float4& a, float4& b, float v, uint4 u) {
    float2 f0 = __half22float2(*reinterpret_cast<__half2*>(&u.x));
    float2 f1 = __half22float2(*reinterpret_cast<__half2*>(&u.y));
    float2 f2 = __half22float2(*reinterpret_cast<__half2*>(&u.z));
    float2 f3 = __half22float2(*reinterpret_cast<__half2*>(&u.w));
    a.x += v * f0.x; a.y += v * f0.y; a.z += v * f1.x; a.w += v * f1.y;
    b.x += v * f2.x; b.y += v * f2.y; b.z += v * f3.x; b.w += v * f3.y;
}

// ================= K_setup: init E + zero cnt + win_reset + wsplit + mlp ======
__global__ void __launch_bounds__(256) k_setup(
    const float4* __restrict__ ue, const float4* __restrict__ ie,
    const int* __restrict__ ui,
    const float* __restrict__ w1, const float* __restrict__ w2,
    const float* __restrict__ feat,
    const float* __restrict__ l1w, const float* __restrict__ l1b,
    const float* __restrict__ l2w, const float* __restrict__ l2b) {
    int b = blockIdx.x;
    int t = threadIdx.x;
    if (b < NB_INIT) {                                   // ---- E init (fp32+fp16)
        int i = b * 256 + t;
        const int NU4 = N_USER * 16;
        if (i >= N_NODES * 16) return;
        float4 v = (i < NU4) ? ue[i] : ie[i - NU4];
        g_E[i] = v;
        g_Eh[i] = pack_half4(v);
        return;
    }
    b -= NB_INIT;
    if (b < NB_SCAN) {                                   // ---- cnt zero
        int i = b * 256 + t;
        if (i < N_NODES) g_cnt[i] = 0;
        return;
    }
    b -= NB_SCAN;
    if (b < 4) {                                         // ---- win reset
        int i = b * 256 + t;
        if (i < BB) g_win[ui[i]] = -1;
        return;
    }
    b -= 4;
    if (b < NB_WSPLIT) {                                 // ---- w split
        int idx = b * 256 + t;
        if (idx >= NLAYER * 64 * 64) return;
        int layer = idx / 4096;
        int rem = idx % 4096;
        int n = rem >> 6, p = rem & 63;
        int k0 = 2 * p, k1 = 2 * p + 1;
        float wa = (k0 < 64) ? w1[layer * 4096 + k0 * 64 + n]
                             : w2[layer * 4096 + (k0 - 64) * 64 + n];
        float wb = (k1 < 64) ? w1[layer * 4096 + k1 * 64 + n]
                             : w2[layer * 4096 + (k1 - 64) * 64 + n];
        unsigned int hi, lo;
        split_pack(wa, wb, hi, lo);
        g_whiB[layer * 64 * WPITCHB + n * WPITCHB + p] = hi;
        g_wloB[layer * 64 * WPITCHB + n * WPITCHB + p] = lo;
        return;
    }
    b -= NB_WSPLIT;
    {                                                    // ---- mlp (4 samples/block)
        __shared__ float h[4][32];
        int s = t >> 6, u = t & 63;                      // sample slot, within
        int i = b * 4 + s;
        if (u < 32) {
            float acc = l1b[u];
#pragma unroll
            for (int f = 0; f < 4; f++) acc += feat[i * 4 + f] * l1w[f * 32 + u];
            h[s][u] = acc;
        }
        __syncthreads();
        float acc = l2b[u];
#pragma unroll
        for (int j = 0; j < 32; j++) acc += h[s][j] * l2w[j * DD + u];
        g_mlp[i * DD + u] = acc;
    }
}

// ================= K_hist2: histogram + win_max ===============================
__global__ void __launch_bounds__(256) k_hist2(const int* __restrict__ row,
                                               const int* __restrict__ ui) {
    int b = blockIdx.x;
    int t = threadIdx.x;
    if (b < NB_HIST) {
        int e = b * 256 + t;
        if (e < NNZ) atomicAdd(&g_cnt[row[e]], 1);
        return;
    }
    b -= NB_HIST;
    int i = b * 256 + t;
    if (i < BB) atomicMax(&g_win[ui[i]], i);
}

// ================= scans =================
__global__ void k_scan1() {
    __shared__ int s[256];
    int t = threadIdx.x;
    int i = blockIdx.x * 256 + t;
    int v = (i < N_NODES) ? g_cnt[i] : 0;
    s[t] = v;
    __syncthreads();
#pragma unroll
    for (int off = 1; off < 256; off <<= 1) {
        int u = (t >= off) ? s[t - off] : 0;
        __syncthreads();
        s[t] += u;
        __syncthreads();
    }
    if (i < N_NODES) g_ptr[i] = s[t] - v;
    if (t == 255) g_bsum[blockIdx.x] = s[255];
}
__global__ void k_scan2() {
    __shared__ int s[1024];
    int t = threadIdx.x;
    int v = (t < NB_SCAN) ? g_bsum[t] : 0;
    s[t] = v;
    __syncthreads();
#pragma unroll
    for (int off = 1; off < 1024; off <<= 1) {
        int u = (t >= off) ? s[t - off] : 0;
        __syncthreads();
        s[t] += u;
        __syncthreads();
    }
    if (t < NB_SCAN) g_bscan[t] = s[t] - v;
}
__global__ void k_scan3() {
    int i = blockIdx.x * blockDim.x + threadIdx.x;
    if (i < N_NODES) {
        int p = g_ptr[i] + g_bscan[i >> 8];
        g_ptr[i] = p;
        g_cur[i] = p;
    }
}

// ================= K_fill2: CSR fill + user-update apply ======================
__global__ void __launch_bounds__(256) k_fill2(const int* __restrict__ row,
                                               const int* __restrict__ col,
                                               const float* __restrict__ val,
                                               const int* __restrict__ ui,
                                               const float* __restrict__ user_emb,
                                               const float* __restrict__ ratio) {
    int b = blockIdx.x;
    int t = threadIdx.x;
    if (b < NB_HIST) {                                   // ---- fill
        int e = b * 256 + t;
        if (e >= NNZ) return;
        int r = row[e];
        int pos = atomicAdd(&g_cur[r], 1);
        g_cv[pos] = make_int2(col[e], __float_as_int(val[e]));
        return;
    }
    b -= NB_HIST;
    {                                                    // ---- apply (4 samples/block)
        int s = t >> 6, u64 = t & 63;
        int i = b * 4 + s;
        int u = ui[i];
        if (g_win[u] != i) return;
        float r = *ratio;
        float* E = (float*)g_E;
        float v = user_emb[u * DD + u64] * (1.0f - r) + g_mlp[i * DD + u64] * r;
        E[u * DD + u64] = v;
        ((__half*)g_Eh)[u * DD + u64] = __float2half_rn(v);
    }
}

// ---------------- gather body (device fn) ----------------
__device__ __forceinline__ void gather_body(int w, int lane,
                                            const int* __restrict__ user_idx,
                                            const int* __restrict__ pos_idx,
                                            const int* __restrict__ neg_idx,
                                            float* __restrict__ out, int layer) {
    if (w >= 3 * BB) return;
    int node;
    if (w < BB)          node = user_idx[w];
    else if (w < 2 * BB) node = N_USER + pos_idx[w - BB];
    else                 node = N_USER + neg_idx[w - 2 * BB];
    float2 v = ((const float2*)g_E)[node * 32 + lane];
    float scale = 1.0f;
    if (layer > 0) {
        float s = v.x * v.x + v.y * v.y;
#pragma unroll
        for (int o = 16; o; o >>= 1) s += __shfl_xor_sync(0xffffffffu, s, o);
        scale = 1.0f / fmaxf(sqrtf(s), 1e-12f);
    }
    ((float2*)(out + (size_t)w * 256 + layer * 64))[lane] = make_float2(v.x * scale, v.y * scale);
}

__global__ void k_gather(const int* __restrict__ user_idx, const int* __restrict__ pos_idx,
                         const int* __restrict__ neg_idx, float* __restrict__ out, int layer) {
    int w = (blockIdx.x * blockDim.x + threadIdx.x) >> 5;
    gather_body(w, threadIdx.x & 31, user_idx, pos_idx, neg_idx, out, layer);
}

// ================= CSR SpMM (fp16 gather): 4 rows/warp, 8 lanes x uint4/row ===
// blocks [0, NB_SPMM): spmm; blocks [NB_SPMM, +NB_GATHER): gather layer-k input E
__global__ void __launch_bounds__(256) k_spmm_g(const int* __restrict__ user_idx,
                                                const int* __restrict__ pos_idx,
                                                const int* __restrict__ neg_idx,
                                                float* __restrict__ out, int layer) {
    int lane = threadIdx.x & 31;
    if (blockIdx.x >= NB_SPMM) {
        int w = ((blockIdx.x - NB_SPMM) * blockDim.x + threadIdx.x) >> 5;
        gather_body(w, lane, user_idx, pos_idx, neg_idx, out, layer);
        return;
    }
    int w = (blockIdx.x * blockDim.x + threadIdx.x) >> 5;
    int sub = lane >> 3;        // 0..3: row within warp
    int hl = lane & 7;          // uint4 slot within fp16 row (8 halves each)
    int row = w * 4 + sub;
    if (row >= N_NODES) return;
    int start = g_ptr[row];
    int end = start + g_cnt[row];
    const uint4* __restrict__ Eh = (const uint4*)g_Eh;

    float4 aL0 = make_float4(0.f, 0.f, 0.f, 0.f);
    float4 aH0 = make_float4(0.f, 0.f, 0.f, 0.f);
    float4 aL1 = make_float4(0.f, 0.f, 0.f, 0.f);
    float4 aH1 = make_float4(0.f, 0.f, 0.f, 0.f);
    int e = start;
    for (; e + 2 <= end; e += 2) {
        int2 c0 = g_cv[e], c1 = g_cv[e + 1];
        uint4 x0 = Eh[c0.x * 8 + hl];       // full 128B row per 8 lanes
        uint4 x1 = Eh[c1.x * 8 + hl];
        acc8(aL0, aH0, __int_as_float(c0.y), x0);
        acc8(aL1, aH1, __int_as_float(c1.y), x1);
    }
    if (e < end) {
        int2 c0 = g_cv[e];
        uint4 x0 = Eh[c0.x * 8 + hl];
        acc8(aL0, aH0, __int_as_float(c0.y), x0);
    }
    aL0.x += aL1.x; aL0.y += aL1.y; aL0.z += aL1.z; aL0.w += aL1.w;
    aH0.x += aH1.x; aH0.y += aH1.y; aH0.z += aH1.z; aH0.w += aH1.w;
    // lane owns halves [hl*8, hl*8+8) = float4 slots 2*hl, 2*hl+1
    g_LE[row * 16 + 2 * hl] = aL0;
    g_LE[row * 16 + 2 * hl + 1] = aH0;
}

// ================= tensor-core GEMM (bf16 double-split, m16n8k16) =============
#define MMA_BF16(C, A0, A1, A2, A3, B0, B1)                                      \
    asm volatile("mma.sync.aligned.m16n8k16.row.col.f32.bf16.bf16.f32 "          \
                 "{%0,%1,%2,%3}, {%4,%5,%6,%7}, {%8,%9}, {%0,%1,%2,%3};"         \
                 : "+f"(C[0]), "+f"(C[1]), "+f"(C[2]), "+f"(C[3])                \
                 : "r"(A0), "r"(A1), "r"(A2), "r"(A3), "r"(B0), "r"(B1))

__global__ void __launch_bounds__(256) k_gemm_mma(int layer,
                                                  const float* __restrict__ b1,
                                                  const float* __restrict__ b2) {
    __shared__ unsigned int whi[64 * WPITCHB];
    __shared__ float bs[64];
    int t = threadIdx.x;
    {
        const uint4* s4 = (const uint4*)(g_whiB + layer * 64 * WPITCHB);
        uint4* d4 = (uint4*)whi;
        for (int i = t; i < 64 * WPITCHB / 4; i += 256) d4[i] = s4[i];
        if (t < 64) bs[t] = b1[t] + b2[t];
    }
    __syncthreads();

    int warp = t >> 5, lane = t & 31;
    int q = lane & 3, g = lane >> 2;
    int base = blockIdx.x * 128 + warp * 16;
    int r0 = base + g, r1 = base + g + 8;
    int r0c = min(r0, N_NODES - 1), r1c = min(r1, N_NODES - 1);
    const float* __restrict__ Ei = (const float*)g_E;
    const float* __restrict__ LE = (const float*)g_LE;
    const unsigned int* __restrict__ wlo = g_wloB + layer * 64 * WPITCHB;

    float C[8][4];
#pragma unroll
    for (int i = 0; i < 8; i++)
#pragma unroll
        for (int j = 0; j < 4; j++) C[i][j] = 0.f;

#pragma unroll
    for (int kk = 0; kk < 8; kk++) {         // kk16 chunks of K=128
        int half = kk >> 2;                  // 0: (LE+E), 1: (LE*E)
        int cb = (kk & 3) * 16;
        int cA = cb + 2 * q;
        int cB = cA + 8;
        float2 lA0 = *(const float2*)(LE + r0c * 64 + cA);
        float2 lB0 = *(const float2*)(LE + r0c * 64 + cB);
        float2 lA1 = *(const float2*)(LE + r1c * 64 + cA);
        float2 lB1 = *(const float2*)(LE + r1c * 64 + cB);
        float2 eA0 = *(const float2*)(Ei + r0c * 64 + cA);
        float2 eB0 = *(const float2*)(Ei + r0c * 64 + cB);
        float2 eA1 = *(const float2*)(Ei + r1c * 64 + cA);
        float2 eB1 = *(const float2*)(Ei + r1c * 64 + cB);
        float2 xA0, xB0, xA1, xB1;
        if (half) {
            xA0 = make_float2(lA0.x * eA0.x, lA0.y * eA0.y);
            xB0 = make_float2(lB0.x * eB0.x, lB0.y * eB0.y);
            xA1 = make_float2(lA1.x * eA1.x, lA1.y * eA1.y);
            xB1 = make_float2(lB1.x * eB1.x, lB1.y * eB1.y);
        } else {
            xA0 = make_float2(lA0.x + eA0.x, lA0.y + eA0.y);
            xB0 = make_float2(lB0.x + eB0.x, lB0.y + eB0.y);
            xA1 = make_float2(lA1.x + eA1.x, lA1.y + eA1.y);
            xB1 = make_float2(lB1.x + eB1.x, lB1.y + eB1.y);
        }
        unsigned int ah0, ah1, ah2, ah3, al0, al1, al2, al3;
        split_pack(xA0.x, xA0.y, ah0, al0);
        split_pack(xA1.x, xA1.y, ah1, al1);
        split_pack(xB0.x, xB0.y, ah2, al2);
        split_pack(xB1.x, xB1.y, ah3, al3);
        int kp = kk * 8 + q;
#pragma unroll
        for (int nt = 0; nt < 8; nt++) {
            int wb = (nt * 8 + g) * WPITCHB + kp;
            unsigned int bh0 = whi[wb], bh1 = whi[wb + 4];
            unsigned int bl0 = __ldg(&wlo[wb]), bl1 = __ldg(&wlo[wb + 4]);
            MMA_BF16(C[nt], ah0, ah1, ah2, ah3, bh0, bh1);
            MMA_BF16(C[nt], al0, al1, al2, al3, bh0, bh1);
            MMA_BF16(C[nt], ah0, ah1, ah2, ah3, bl0, bl1);
        }
    }

    float* Eo = (float*)g_E;
    __half2* Eoh = (__half2*)g_Eh;
#pragma unroll
    for (int nt = 0; nt < 8; nt++) {
        int col = nt * 8 + 2 * q;
        float b0v = bs[col], b1v = bs[col + 1];
        float v00 = C[nt][0] + b0v, v01 = C[nt][1] + b1v;
        float v10 = C[nt][2] + b0v, v11 = C[nt][3] + b1v;
        v00 = v00 >= 0.f ? v00 : 0.2f * v00;
        v01 = v01 >= 0.f ? v01 : 0.2f * v01;
        v10 = v10 >= 0.f ? v10 : 0.2f * v10;
        v11 = v11 >= 0.f ? v11 : 0.2f * v11;
        if (r0 < N_NODES) {
            *(float2*)(Eo + r0 * 64 + col) = make_float2(v00, v01);
            Eoh[r0 * 32 + col / 2] = __floats2half2_rn(v00, v01);
        }
        if (r1 < N_NODES) {
            *(float2*)(Eo + r1 * 64 + col) = make_float2(v10, v11);
            Eoh[r1 * 32 + col / 2] = __floats2half2_rn(v10, v11);
        }
    }
}

extern "C" void kernel_launch(void* const* d_in, const int* in_sizes, int n_in,
                              void* d_out, int out_size) {
    const float *user_emb, *item_emb, *lin1_w, *lin1_b, *lin2_w, *lin2_b;
    const float *w1, *b1, *w2, *b2, *lap_val, *user_feat, *mlp_ratio;
    const int *lap_row, *lap_col, *user_idx, *pos_idx, *neg_idx;

    if (in_sizes[2] == 4096) {
        user_emb = (const float*)d_in[0];  item_emb = (const float*)d_in[1];
        user_feat= (const float*)d_in[2];
        lin1_w   = (const float*)d_in[3];  lin1_b   = (const float*)d_in[4];
        lin2_w   = (const float*)d_in[5];  lin2_b   = (const float*)d_in[6];
        w1 = (const float*)d_in[7];  b1 = (const float*)d_in[8];
        w2 = (const float*)d_in[9];  b2 = (const float*)d_in[10];
        lap_val  = (const float*)d_in[11]; mlp_ratio = (const float*)d_in[12];
        lap_row  = (const int*)d_in[13];   lap_col   = (const int*)d_in[14];
        user_idx = (const int*)d_in[15];   pos_idx   = (const int*)d_in[16];
        neg_idx  = (const int*)d_in[17];
    } else {
        user_emb = (const float*)d_in[0];  item_emb = (const float*)d_in[1];
        lin1_w   = (const float*)d_in[2];  lin1_b   = (const float*)d_in[3];
        lin2_w   = (const float*)d_in[4];  lin2_b   = (const float*)d_in[5];
        w1 = (const float*)d_in[6];  b1 = (const float*)d_in[7];
        w2 = (const float*)d_in[8];  b2 = (const float*)d_in[9];
        lap_row  = (const int*)d_in[10];   lap_col  = (const int*)d_in[11];
        lap_val  = (const float*)d_in[12];
        user_idx = (const int*)d_in[13];   user_feat = (const float*)d_in[14];
        pos_idx  = (const int*)d_in[15];   neg_idx   = (const int*)d_in[16];
        mlp_ratio= (const float*)d_in[17];
    }

    float* out = (float*)d_out;

    // phase 1: all independent setup work in one launch
    k_setup<<<NB_INIT + NB_SCAN + 4 + NB_WSPLIT + NB_MLP, 256>>>(
        (const float4*)user_emb, (const float4*)item_emb, user_idx,
        w1, w2, user_feat, lin1_w, lin1_b, lin2_w, lin2_b);
    // phase 2: histogram + winner selection
    k_hist2<<<NB_HIST + 4, 256>>>(lap_row, user_idx);
    // phase 3: scan chain
    k_scan1<<<NB_SCAN, 256>>>();
    k_scan2<<<1, 1024>>>();
    k_scan3<<<NB_SCAN, 256>>>();
    // phase 4: CSR fill + user-update apply
    k_fill2<<<NB_HIST + NB_APPLY, 256>>>(lap_row, lap_col, lap_val,
                                         user_idx, user_emb, mlp_ratio);

    for (int k = 0; k < NLAYER; k++) {
        // spmm(k) fused with gather of layer-k input E (valid for k=0 too:
        // both spmm and gather only READ post-apply E; layer=0 skips norm)
        k_spmm_g<<<NB_SPMM + NB_GATHER, 256>>>(user_idx, pos_idx, neg_idx, out, k);
        k_gemm_mma<<<(N_NODES + 127) / 128, 256>>>(k, b1 + k * 64, b2 + k * 64);
    }
    // final gather after last gemm
    k_gather<<<NB_GATHER, 256>>>(user_idx, pos_idx, neg_idx, out, NLAYER);
}